// round 1
// baseline (speedup 1.0000x reference)
#include <cuda_runtime.h>

#define BB 256
#define NSTEP 32
#define NIMG (NSTEP*BB)   // 8192

// out layout: [0, 81920) digit probs (img-major, 10 each)
//             [81920, 81920+49152) guard probs (img-major, 6 each)
//             [131072, 133632) final state (b-major, 10 each)
#define OUT_GUARD 81920
#define OUT_STATE (81920 + 49152)

__global__ __launch_bounds__(256) void cnn_kernel(
    const float* __restrict__ seq,
    const float* __restrict__ w1, const float* __restrict__ b1,
    const float* __restrict__ w2, const float* __restrict__ b2,
    const float* __restrict__ w3, const float* __restrict__ b3,
    const float* __restrict__ wd, const float* __restrict__ bd,
    float* __restrict__ out)
{
    __shared__ float sw1[72],  sb1[8];
    __shared__ float sw2[1152], sb2[16];
    __shared__ float sw3[4608], sb3[32];
    __shared__ float swd[320], sbd[10];
    __shared__ float sin_[784];
    __shared__ float p1[1352];   // 8 x 13 x 13
    __shared__ float p2[400];    // 16 x 5 x 5
    __shared__ float c3buf[128]; // 32 oc x 4 positions
    __shared__ float p3[32];
    __shared__ float logit[10], eprob[10], prob[10];

    const int tid = threadIdx.x;
    const int img = blockIdx.x;
    const int b = img & 255;
    const int n = img >> 8;
    const float* in = seq + (size_t)(b * 32 + n) * 784;

    // ---- cooperative loads: weights + input ----
    for (int i = tid; i < 72;   i += 256) sw1[i] = w1[i];
    for (int i = tid; i < 1152; i += 256) sw2[i] = w2[i];
    for (int i = tid; i < 4608; i += 256) sw3[i] = w3[i];
    for (int i = tid; i < 320;  i += 256) swd[i] = wd[i];
    for (int i = tid; i < 784;  i += 256) sin_[i] = in[i];
    if (tid < 8)  sb1[tid] = b1[tid];
    if (tid < 16) sb2[tid] = b2[tid];
    if (tid < 32) sb3[tid] = b3[tid];
    if (tid < 10) sbd[tid] = bd[tid];
    __syncthreads();

    // ---- stage 1: conv1(1->8, 3x3) + relu + avgpool2 -> p1 (8,13,13) ----
    for (int idx = tid; idx < 1352; idx += 256) {
        int c = idx / 169, rem = idx % 169;
        int py = rem / 13, px = rem % 13;
        int y0 = 2 * py, x0 = 2 * px;
        float patch[4][4];
        #pragma unroll
        for (int r = 0; r < 4; r++)
            #pragma unroll
            for (int cc = 0; cc < 4; cc++)
                patch[r][cc] = sin_[(y0 + r) * 28 + x0 + cc];
        float w[9];
        #pragma unroll
        for (int k = 0; k < 9; k++) w[k] = sw1[c * 9 + k];
        float bias = sb1[c];
        float s00 = bias, s01 = bias, s10 = bias, s11 = bias;
        #pragma unroll
        for (int ky = 0; ky < 3; ky++)
            #pragma unroll
            for (int kx = 0; kx < 3; kx++) {
                float wv = w[ky * 3 + kx];
                s00 += patch[ky][kx] * wv;
                s01 += patch[ky][kx + 1] * wv;
                s10 += patch[ky + 1][kx] * wv;
                s11 += patch[ky + 1][kx + 1] * wv;
            }
        p1[idx] = 0.25f * (fmaxf(s00, 0.f) + fmaxf(s01, 0.f) +
                           fmaxf(s10, 0.f) + fmaxf(s11, 0.f));
    }
    __syncthreads();

    // ---- stage 2: conv2(8->16, 3x3) + relu + avgpool2 -> p2 (16,5,5) ----
    for (int idx = tid; idx < 400; idx += 256) {
        int oc = idx / 25, rem = idx % 25;
        int py = rem / 5, px = rem % 5;
        int y0 = 2 * py, x0 = 2 * px;
        float bias = sb2[oc];
        float s00 = bias, s01 = bias, s10 = bias, s11 = bias;
        for (int ic = 0; ic < 8; ic++) {
            const float* pin = &p1[ic * 169];
            const float* wp = &sw2[(oc * 8 + ic) * 9];
            float patch[4][4];
            #pragma unroll
            for (int r = 0; r < 4; r++)
                #pragma unroll
                for (int cc = 0; cc < 4; cc++)
                    patch[r][cc] = pin[(y0 + r) * 13 + x0 + cc];
            float w[9];
            #pragma unroll
            for (int k = 0; k < 9; k++) w[k] = wp[k];
            #pragma unroll
            for (int ky = 0; ky < 3; ky++)
                #pragma unroll
                for (int kx = 0; kx < 3; kx++) {
                    float wv = w[ky * 3 + kx];
                    s00 += patch[ky][kx] * wv;
                    s01 += patch[ky][kx + 1] * wv;
                    s10 += patch[ky + 1][kx] * wv;
                    s11 += patch[ky + 1][kx + 1] * wv;
                }
        }
        p2[idx] = 0.25f * (fmaxf(s00, 0.f) + fmaxf(s01, 0.f) +
                           fmaxf(s10, 0.f) + fmaxf(s11, 0.f));
    }
    __syncthreads();

    // ---- stage 3: conv3(16->32, 3x3) + relu (3x3 out) + avgpool2 -> p3 (32) ----
    if (tid < 128) {
        int oc = tid >> 2, pos = tid & 3;
        int y0 = pos >> 1, x0 = pos & 1;
        float s = sb3[oc];
        for (int ic = 0; ic < 16; ic++) {
            const float* pin = &p2[ic * 25];
            const float* wp = &sw3[(oc * 16 + ic) * 9];
            #pragma unroll
            for (int ky = 0; ky < 3; ky++)
                #pragma unroll
                for (int kx = 0; kx < 3; kx++)
                    s += pin[(y0 + ky) * 5 + x0 + kx] * wp[ky * 3 + kx];
        }
        c3buf[tid] = fmaxf(s, 0.f);
    }
    __syncthreads();
    if (tid < 32)
        p3[tid] = 0.25f * (c3buf[tid * 4] + c3buf[tid * 4 + 1] +
                           c3buf[tid * 4 + 2] + c3buf[tid * 4 + 3]);
    __syncthreads();

    // ---- stage 4: dense (32->10) + softmax + guard ----
    if (tid < 10) {
        float s = sbd[tid];
        #pragma unroll
        for (int c = 0; c < 32; c++) s += p3[c] * swd[tid * 32 + c];
        logit[tid] = s;
    }
    __syncthreads();
    if (tid < 10) {
        float m = logit[0];
        #pragma unroll
        for (int j = 1; j < 10; j++) m = fmaxf(m, logit[j]);
        eprob[tid] = __expf(logit[tid] - m);
    }
    __syncthreads();
    if (tid < 10) {
        float sum = 0.f;
        #pragma unroll
        for (int j = 0; j < 10; j++) sum += eprob[j];
        float p = eprob[tid] / sum;
        prob[tid] = p;
        out[(size_t)img * 10 + tid] = p;
    }
    __syncthreads();
    if (tid < 6) {
        float g;
        if      (tid == 0) g = prob[8];
        else if (tid == 1) g = prob[4] + prob[6];
        else if (tid == 2) g = prob[0] + prob[2];
        else if (tid == 3) g = prob[7] + prob[9];
        else if (tid == 4) g = prob[5];
        else               g = prob[1] + prob[3];
        out[OUT_GUARD + (size_t)img * 6 + tid] = g;
    }
}

__global__ __launch_bounds__(64) void sfa_kernel(
    const float* __restrict__ trans,
    const float* __restrict__ guard,   // out + OUT_GUARD
    float* __restrict__ out_state)     // out + OUT_STATE
{
    __shared__ float M[600];           // [r][i][j] = M[(r*10+i)*10 + j]
    __shared__ float st[2][10];
    __shared__ float g[6];

    const int tid = threadIdx.x;
    const int b = blockIdx.x;

    // tempered softmax rows of trans: M[r][i][:] for i<9
    for (int item = tid; item < 54; item += 64) {
        int r = item / 9, i = item % 9;
        const float* row = trans + (size_t)(r * 9 + i) * 10;
        float v[10];
        float m = -1e30f;
        #pragma unroll
        for (int j = 0; j < 10; j++) { v[j] = row[j] * 10.0f; m = fmaxf(m, v[j]); }
        float s = 0.f;
        #pragma unroll
        for (int j = 0; j < 10; j++) { v[j] = __expf(v[j] - m); s += v[j]; }
        float inv = 1.0f / s;
        #pragma unroll
        for (int j = 0; j < 10; j++) M[(r * 10 + i) * 10 + j] = v[j] * inv;
    }
    // accepting row: M[r][9][j] = (j==9)
    if (tid < 6) {
        #pragma unroll
        for (int j = 0; j < 10; j++) M[(tid * 10 + 9) * 10 + j] = (j == 9) ? 1.f : 0.f;
    }
    if (tid < 10) st[0][tid] = (tid == 0) ? 1.f : 0.f;
    __syncthreads();

    int cur = 0;
    for (int n = 0; n < NSTEP; n++) {
        if (tid < 6) g[tid] = guard[(size_t)(n * BB + b) * 6 + tid];
        __syncthreads();
        if (tid < 10) {
            float ns = 0.f;
            #pragma unroll
            for (int i = 0; i < 10; i++) {
                float a = 0.f;
                #pragma unroll
                for (int r = 0; r < 6; r++) a += g[r] * M[(r * 10 + i) * 10 + tid];
                ns += st[cur][i] * a;
            }
            st[cur ^ 1][tid] = ns;
        }
        cur ^= 1;
        __syncthreads();
    }
    if (tid < 10) out_state[b * 10 + tid] = st[cur][tid];
}

extern "C" void kernel_launch(void* const* d_in, const int* in_sizes, int n_in,
                              void* d_out, int out_size)
{
    const float* seq = (const float*)d_in[0];
    const float* w1  = (const float*)d_in[1];
    const float* b1  = (const float*)d_in[2];
    const float* w2  = (const float*)d_in[3];
    const float* b2  = (const float*)d_in[4];
    const float* w3  = (const float*)d_in[5];
    const float* b3  = (const float*)d_in[6];
    const float* wd  = (const float*)d_in[7];
    const float* bd  = (const float*)d_in[8];
    const float* tr  = (const float*)d_in[9];
    float* out = (float*)d_out;

    cnn_kernel<<<NIMG, 256>>>(seq, w1, b1, w2, b2, w3, b3, wd, bd, out);
    sfa_kernel<<<BB, 64>>>(tr, out + OUT_GUARD, out + OUT_STATE);
}

// round 2
// speedup vs baseline: 3.9767x; 3.9767x over previous
#include <cuda_runtime.h>

#define BB 256
#define NSTEP 32
#define NIMG (NSTEP*BB)   // 8192

#define OUT_GUARD 81920
#define OUT_STATE (81920 + 49152)

// ---------------- smem layout (floats) for cnn kernel ----------------
#define OFF_W1 0        // 72
#define OFF_B1 72       // 8
#define OFF_W2 80       // 1152
#define OFF_B2 1232     // 16
#define OFF_W3 1248     // 32 oc * 145 (padded from 144)
#define OFF_B3 5888     // 32
#define OFF_WD 5920     // 10 * 33 (padded from 32)
#define OFF_BD 6250     // 10
#define OFF_WB 6272     // per-warp buffers
#define WBSTRIDE 2248   // per-warp floats: sin 784 | p1 1456 ; p2 480 overlays sin; scratch at 480..544
#define SMEM_FLOATS (OFF_WB + 8*WBSTRIDE)   // 24256 floats = 97024 B

// packed fp32x2 FMA (sm_103a)
__device__ __forceinline__ float2 ffma2(float2 a, float2 b, float2 c) {
    unsigned long long A = *reinterpret_cast<unsigned long long*>(&a);
    unsigned long long Bv = *reinterpret_cast<unsigned long long*>(&b);
    unsigned long long C = *reinterpret_cast<unsigned long long*>(&c);
    unsigned long long D;
    asm("fma.rn.f32x2 %0, %1, %2, %3;" : "=l"(D) : "l"(A), "l"(Bv), "l"(C));
    return *reinterpret_cast<float2*>(&D);
}

__global__ __launch_bounds__(256, 2) void cnn_kernel(
    const float* __restrict__ seq,
    const float* __restrict__ w1, const float* __restrict__ b1,
    const float* __restrict__ w2, const float* __restrict__ b2,
    const float* __restrict__ w3, const float* __restrict__ b3,
    const float* __restrict__ wd, const float* __restrict__ bd,
    float* __restrict__ out)
{
    extern __shared__ float sm[];
    const int tid = threadIdx.x;
    const int warp = tid >> 5;
    const int lane = tid & 31;

    // ---- cooperative weight staging (once per block, amortized over 8 images) ----
    for (int i = tid; i < 72;   i += 256) sm[OFF_W1 + i] = w1[i];
    for (int i = tid; i < 1152; i += 256) sm[OFF_W2 + i] = w2[i];
    for (int i = tid; i < 4608; i += 256) {
        int oc = i / 144, r = i - oc * 144;
        sm[OFF_W3 + oc * 145 + r] = w3[i];           // pad: conflict-free in stage3
    }
    for (int i = tid; i < 320; i += 256) {
        int d = i >> 5, c = i & 31;
        sm[OFF_WD + d * 33 + c] = wd[i];
    }
    if (tid < 8)  sm[OFF_B1 + tid] = b1[tid];
    if (tid < 16) sm[OFF_B2 + tid] = b2[tid];
    if (tid < 32) sm[OFF_B3 + tid] = b3[tid];
    if (tid < 10) sm[OFF_BD + tid] = bd[tid];
    __syncthreads();

    // ---- per-warp image ----
    const int img = blockIdx.x * 8 + warp;
    const int b = img & 255;
    const int n = img >> 8;
    float* wb   = sm + OFF_WB + warp * WBSTRIDE;
    float* sin_ = wb;            // 784 (dead after stage1)
    float* p1   = wb + 784;      // 8 x 13 x 14 (row-padded)
    float* p2   = wb;            // 16 x 5 x 6 (row-padded), overlays sin
    float* scr  = wb + 480;      // scratch: 32 v + 10 probs

    // load image (float4)
    {
        const float4* in4 = (const float4*)(seq + (size_t)(b * 32 + n) * 784);
        float4* s4 = (float4*)sin_;
        for (int i = lane; i < 196; i += 32) s4[i] = in4[i];
    }
    __syncwarp();

    // ---- stage 1: conv1(1->8) + relu + pool -> p1 ----
    for (int pos = lane; pos < 169; pos += 32) {
        int py = pos / 13, px = pos - py * 13;
        const float* base = sin_ + (py * 56 + px * 2);   // y0=2py row stride 28
        float2 ra[4], rb[4], mi[4];
        #pragma unroll
        for (int r = 0; r < 4; r++) {
            ra[r] = *(const float2*)(base + r * 28);
            rb[r] = *(const float2*)(base + r * 28 + 2);
            mi[r] = make_float2(ra[r].y, rb[r].x);
        }
        #pragma unroll
        for (int c = 0; c < 8; c++) {
            const float* w = sm + OFF_W1 + c * 9;
            float bias = sm[OFF_B1 + c];
            float2 at = make_float2(bias, bias);
            float2 ab = at;
            #pragma unroll
            for (int ky = 0; ky < 3; ky++) {
                float w0 = w[ky * 3 + 0], w1v = w[ky * 3 + 1], w2v = w[ky * 3 + 2];
                at = ffma2(ra[ky], make_float2(w0, w0), at);
                at = ffma2(mi[ky], make_float2(w1v, w1v), at);
                at = ffma2(rb[ky], make_float2(w2v, w2v), at);
                ab = ffma2(ra[ky + 1], make_float2(w0, w0), ab);
                ab = ffma2(mi[ky + 1], make_float2(w1v, w1v), ab);
                ab = ffma2(rb[ky + 1], make_float2(w2v, w2v), ab);
            }
            p1[c * 182 + py * 14 + px] =
                0.25f * (fmaxf(at.x, 0.f) + fmaxf(at.y, 0.f) +
                         fmaxf(ab.x, 0.f) + fmaxf(ab.y, 0.f));
        }
    }
    __syncwarp();

    // ---- stage 2: conv2(8->16) + relu + pool -> p2 ----
    if (lane < 25) {
        int py = lane / 5, px = lane - py * 5;
        #pragma unroll
        for (int ocb = 0; ocb < 2; ocb++) {
            float2 at[8], ab[8];
            #pragma unroll
            for (int o = 0; o < 8; o++) {
                float bias = sm[OFF_B2 + ocb * 8 + o];
                at[o] = make_float2(bias, bias);
                ab[o] = at[o];
            }
            for (int ic = 0; ic < 8; ic++) {
                const float* pin = p1 + ic * 182 + py * 28 + px * 2;   // y0=2py stride 14
                float2 ra[4], rb[4], mi[4];
                #pragma unroll
                for (int r = 0; r < 4; r++) {
                    ra[r] = *(const float2*)(pin + r * 14);
                    rb[r] = *(const float2*)(pin + r * 14 + 2);
                    mi[r] = make_float2(ra[r].y, rb[r].x);
                }
                #pragma unroll
                for (int o = 0; o < 8; o++) {
                    const float* w = sm + OFF_W2 + ((ocb * 8 + o) * 8 + ic) * 9;
                    #pragma unroll
                    for (int ky = 0; ky < 3; ky++) {
                        float w0 = w[ky * 3 + 0], w1v = w[ky * 3 + 1], w2v = w[ky * 3 + 2];
                        at[o] = ffma2(ra[ky], make_float2(w0, w0), at[o]);
                        at[o] = ffma2(mi[ky], make_float2(w1v, w1v), at[o]);
                        at[o] = ffma2(rb[ky], make_float2(w2v, w2v), at[o]);
                        ab[o] = ffma2(ra[ky + 1], make_float2(w0, w0), ab[o]);
                        ab[o] = ffma2(mi[ky + 1], make_float2(w1v, w1v), ab[o]);
                        ab[o] = ffma2(rb[ky + 1], make_float2(w2v, w2v), ab[o]);
                    }
                }
            }
            #pragma unroll
            for (int o = 0; o < 8; o++)
                p2[(ocb * 8 + o) * 30 + py * 6 + px] =
                    0.25f * (fmaxf(at[o].x, 0.f) + fmaxf(at[o].y, 0.f) +
                             fmaxf(ab[o].x, 0.f) + fmaxf(ab[o].y, 0.f));
        }
    }
    __syncwarp();

    // ---- stage 3: conv3(16->32) + relu + pool -> v (lane = oc) ----
    float v;
    {
        float bias = sm[OFF_B3 + lane];
        float2 at = make_float2(bias, bias);
        float2 ab = at;
        const float* w = sm + OFF_W3 + lane * 145;   // conflict-free (145 odd)
        for (int ic = 0; ic < 16; ic++) {
            const float* pin = p2 + ic * 30;          // rows 0..3, cols 0..3, stride 6
            float2 ra[4], rb[4], mi[4];
            #pragma unroll
            for (int r = 0; r < 4; r++) {
                ra[r] = *(const float2*)(pin + r * 6);
                rb[r] = *(const float2*)(pin + r * 6 + 2);
                mi[r] = make_float2(ra[r].y, rb[r].x);
            }
            const float* wi = w + ic * 9;
            #pragma unroll
            for (int ky = 0; ky < 3; ky++) {
                float w0 = wi[ky * 3 + 0], w1v = wi[ky * 3 + 1], w2v = wi[ky * 3 + 2];
                at = ffma2(ra[ky], make_float2(w0, w0), at);
                at = ffma2(mi[ky], make_float2(w1v, w1v), at);
                at = ffma2(rb[ky], make_float2(w2v, w2v), at);
                ab = ffma2(ra[ky + 1], make_float2(w0, w0), ab);
                ab = ffma2(mi[ky + 1], make_float2(w1v, w1v), ab);
                ab = ffma2(rb[ky + 1], make_float2(w2v, w2v), ab);
            }
        }
        v = 0.25f * (fmaxf(at.x, 0.f) + fmaxf(at.y, 0.f) +
                     fmaxf(ab.x, 0.f) + fmaxf(ab.y, 0.f));
    }
    scr[lane] = v;
    __syncwarp();

    // ---- stage 4: dense + softmax + guards ----
    float logit = 0.f;
    if (lane < 10) {
        logit = sm[OFF_BD + lane];
        const float* w = sm + OFF_WD + lane * 33;
        #pragma unroll
        for (int c = 0; c < 32; c++) logit += scr[c] * w[c];
    }
    float lm = (lane < 10) ? logit : -1e30f;
    #pragma unroll
    for (int o = 16; o > 0; o >>= 1) lm = fmaxf(lm, __shfl_xor_sync(0xffffffffu, lm, o));
    float e = (lane < 10) ? __expf(logit - lm) : 0.f;
    float s = e;
    #pragma unroll
    for (int o = 16; o > 0; o >>= 1) s += __shfl_xor_sync(0xffffffffu, s, o);
    float prob = e / s;
    if (lane < 10) {
        out[(size_t)img * 10 + lane] = prob;
        scr[32 + lane] = prob;
    }
    __syncwarp();
    if (lane < 6) {
        const float* p = scr + 32;
        float g;
        if      (lane == 0) g = p[8];
        else if (lane == 1) g = p[4] + p[6];
        else if (lane == 2) g = p[0] + p[2];
        else if (lane == 3) g = p[7] + p[9];
        else if (lane == 4) g = p[5];
        else                g = p[1] + p[3];
        out[OUT_GUARD + (size_t)img * 6 + lane] = g;
    }
}

// ---------------- SFA: warp per batch element, 32 blocks x 8 warps ----------------
__global__ __launch_bounds__(256) void sfa_kernel(
    const float* __restrict__ trans,
    const float* __restrict__ guard,
    float* __restrict__ out_state)
{
    __shared__ float M[600];          // [r][i][j]
    __shared__ float gb[8][192];      // per-warp prefetched guards [n][r]
    __shared__ float stg[8][10];      // per-warp state staging

    const int tid = threadIdx.x;
    const int warp = tid >> 5;
    const int lane = tid & 31;

    // tempered softmax rows (54) + accepting rows (6)
    if (tid < 54) {
        int r = tid / 9, i = tid - r * 9;
        const float* row = trans + (size_t)(r * 9 + i) * 10;
        float vv[10];
        float m = -1e30f;
        #pragma unroll
        for (int j = 0; j < 10; j++) { vv[j] = row[j] * 10.0f; m = fmaxf(m, vv[j]); }
        float s = 0.f;
        #pragma unroll
        for (int j = 0; j < 10; j++) { vv[j] = __expf(vv[j] - m); s += vv[j]; }
        float inv = 1.0f / s;
        #pragma unroll
        for (int j = 0; j < 10; j++) M[(r * 10 + i) * 10 + j] = vv[j] * inv;
    } else if (tid < 60) {
        int r = tid - 54;
        #pragma unroll
        for (int j = 0; j < 10; j++) M[(r * 10 + 9) * 10 + j] = (j == 9) ? 1.f : 0.f;
    }

    const int b = blockIdx.x * 8 + warp;
    // prefetch 32 steps x 6 guards (lane = step)
    #pragma unroll
    for (int r = 0; r < 6; r++)
        gb[warp][lane * 6 + r] = guard[((size_t)lane * 256 + b) * 6 + r];
    __syncthreads();

    float st = (lane == 0) ? 1.f : 0.f;
    for (int nn = 0; nn < NSTEP; nn++) {
        if (lane < 10) stg[warp][lane] = st;
        __syncwarp();
        float ns = 0.f;
        if (lane < 10) {
            const float* gn = gb[warp] + nn * 6;
            #pragma unroll
            for (int i = 0; i < 10; i++) {
                float a = 0.f;
                #pragma unroll
                for (int r = 0; r < 6; r++) a += gn[r] * M[(r * 10 + i) * 10 + lane];
                ns += stg[warp][i] * a;
            }
        }
        st = ns;
        __syncwarp();
    }
    if (lane < 10) out_state[b * 10 + lane] = st;
}

extern "C" void kernel_launch(void* const* d_in, const int* in_sizes, int n_in,
                              void* d_out, int out_size)
{
    const float* seq = (const float*)d_in[0];
    const float* w1  = (const float*)d_in[1];
    const float* b1  = (const float*)d_in[2];
    const float* w2  = (const float*)d_in[3];
    const float* b2  = (const float*)d_in[4];
    const float* w3  = (const float*)d_in[5];
    const float* b3  = (const float*)d_in[6];
    const float* wd  = (const float*)d_in[7];
    const float* bd  = (const float*)d_in[8];
    const float* tr  = (const float*)d_in[9];
    float* out = (float*)d_out;

    static int smem_set = 0;
    if (!smem_set) {
        cudaFuncSetAttribute(cnn_kernel, cudaFuncAttributeMaxDynamicSharedMemorySize,
                             SMEM_FLOATS * sizeof(float));
        smem_set = 1;
    }
    cnn_kernel<<<NIMG / 8, 256, SMEM_FLOATS * sizeof(float)>>>(
        seq, w1, b1, w2, b2, w3, b3, wd, bd, out);
    sfa_kernel<<<BB / 8, 256>>>(tr, out + OUT_GUARD, out + OUT_STATE);
}